// round 1
// baseline (speedup 1.0000x reference)
#include <cuda_runtime.h>

#define MAX_N 20000
#define MAX_E 5000
#define FT 128
#define NODE_CAP 128   // max edges per node (mean ~50, 11 sigma headroom)
#define EDGE_CAP 384   // max nodes per edge (mean ~200, 13 sigma headroom)

// ---- scratch (no allocations allowed; __device__ globals) ----
__device__ int   g_dv[MAX_N];                 // node degree (edge count per node)
__device__ int   g_de[MAX_E];                 // edge degree (node count per edge)
__device__ int   g_csr[MAX_N * NODE_CAP];     // edges per node
__device__ int   g_csc[MAX_E * EDGE_CAP];     // nodes per edge
__device__ float g_S[MAX_E * FT];             // S = H^T X
__device__ float g_M[MAX_E * FT];             // M = (S W) / DE

// ---------------------------------------------------------------------------
__global__ void zero_counts(int n_nodes, int n_edges) {
    int i = blockIdx.x * blockDim.x + threadIdx.x;
    if (i < n_nodes) g_dv[i] = 0;
    if (i < n_edges) g_de[i] = 0;
}

// One block per node row of H. Reads the whole 400MB of H exactly once,
// building CSR (per-node edge list via smem counter) and CSC (per-edge node
// list via global atomics) plus both degree counts. HBM-bound.
__global__ __launch_bounds__(256) void build_sparse(const float* __restrict__ H,
                                                    int n_edges) {
    int n = blockIdx.x;
    __shared__ int s_cnt;
    if (threadIdx.x == 0) s_cnt = 0;
    __syncthreads();

    const float4* row = (const float4*)(H + (size_t)n * n_edges);
    int nq = n_edges >> 2;  // n_edges = 5000, divisible by 4
    for (int i = threadIdx.x; i < nq; i += blockDim.x) {
        float4 v = row[i];
        int e0 = i << 2;
        int cnt = (v.x != 0.f) + (v.y != 0.f) + (v.z != 0.f) + (v.w != 0.f);
        if (cnt) {
            int pos = atomicAdd(&s_cnt, cnt);
            int es[4]; int k = 0;
            if (v.x != 0.f) es[k++] = e0;
            if (v.y != 0.f) es[k++] = e0 + 1;
            if (v.z != 0.f) es[k++] = e0 + 2;
            if (v.w != 0.f) es[k++] = e0 + 3;
            #pragma unroll
            for (int j = 0; j < 4; j++) {
                if (j >= k) break;
                int p = pos + j;
                if (p < NODE_CAP) g_csr[n * NODE_CAP + p] = es[j];
                int q = atomicAdd(&g_de[es[j]], 1);
                if (q < EDGE_CAP) g_csc[es[j] * EDGE_CAP + q] = n;
            }
        }
    }
    __syncthreads();
    if (threadIdx.x == 0) g_dv[n] = min(s_cnt, NODE_CAP);
}

// S[e][:] = sum over nodes in edge e of X[n][:]. One block (128 thr) per edge.
// X is 10MB -> L2 resident after first touch; this pass is L2-bandwidth bound.
__global__ __launch_bounds__(FT) void gather_S(const float* __restrict__ X) {
    int e = blockIdx.x;
    int t = threadIdx.x;
    int cnt = min(g_de[e], EDGE_CAP);
    const int* __restrict__ nodes = g_csc + e * EDGE_CAP;
    float acc = 0.f;
    int i = 0;
    for (; i + 4 <= cnt; i += 4) {
        int n0 = nodes[i], n1 = nodes[i + 1], n2 = nodes[i + 2], n3 = nodes[i + 3];
        float a = X[(size_t)n0 * FT + t];
        float b = X[(size_t)n1 * FT + t];
        float c = X[(size_t)n2 * FT + t];
        float d = X[(size_t)n3 * FT + t];
        acc += (a + b) + (c + d);
    }
    for (; i < cnt; i++) acc += X[(size_t)nodes[i] * FT + t];
    g_S[e * FT + t] = acc;
}

// M[e][j] = (sum_k S[e][k] * W[k][j]) / de[e].  Small GEMM: 5000x128x128.
// Block of 128 threads handles 16 edges; S tile in smem, W rows via L1.
__global__ __launch_bounds__(FT) void gemm_M(const float* __restrict__ W,
                                             int n_edges) {
    int e0 = blockIdx.x * 16;
    int j = threadIdx.x;
    __shared__ float Ss[16][FT];
    for (int idx = threadIdx.x; idx < 16 * FT; idx += blockDim.x) {
        int r = idx >> 7, k = idx & (FT - 1);
        Ss[r][k] = (e0 + r < n_edges) ? g_S[(e0 + r) * FT + k] : 0.f;
    }
    __syncthreads();
    float acc[16];
    #pragma unroll
    for (int r = 0; r < 16; r++) acc[r] = 0.f;
    #pragma unroll 4
    for (int k = 0; k < FT; k++) {
        float wv = W[k * FT + j];
        #pragma unroll
        for (int r = 0; r < 16; r++) acc[r] += Ss[r][k] * wv;
    }
    #pragma unroll
    for (int r = 0; r < 16; r++) {
        int e = e0 + r;
        if (e < n_edges) {
            int de = g_de[e];
            g_M[e * FT + j] = (de > 0) ? acc[r] / (float)de : 0.f;
        }
    }
}

// out[n][:] = relu( (sum over edges of node n of M[e][:]) / dv[n] + bias ).
// One block (128 thr) per node. M is 2.5MB -> L2 resident; L2-bound pass.
__global__ __launch_bounds__(FT) void scatter_out(const float* __restrict__ bias,
                                                  float* __restrict__ out) {
    int n = blockIdx.x;
    int t = threadIdx.x;
    int cnt = g_dv[n];
    const int* __restrict__ edges = g_csr + n * NODE_CAP;
    float acc = 0.f;
    int i = 0;
    for (; i + 4 <= cnt; i += 4) {
        int e0 = edges[i], e1 = edges[i + 1], e2 = edges[i + 2], e3 = edges[i + 3];
        float a = g_M[e0 * FT + t];
        float b = g_M[e1 * FT + t];
        float c = g_M[e2 * FT + t];
        float d = g_M[e3 * FT + t];
        acc += (a + b) + (c + d);
    }
    for (; i < cnt; i++) acc += g_M[edges[i] * FT + t];
    float v = (cnt > 0) ? acc / (float)cnt : 0.f;
    v += bias[t];
    out[(size_t)n * FT + t] = v > 0.f ? v : 0.f;
}

// ---------------------------------------------------------------------------
extern "C" void kernel_launch(void* const* d_in, const int* in_sizes, int n_in,
                              void* d_out, int out_size) {
    const float* X  = (const float*)d_in[0];   // [N, 128]
    const float* H  = (const float*)d_in[1];   // [N, E]
    const float* Wt = (const float*)d_in[2];   // [128, 128]
    const float* bs = (const float*)d_in[3];   // [128]
    float* out = (float*)d_out;                // [N, 128]

    int n_nodes = in_sizes[0] / FT;            // 20000
    int n_edges = in_sizes[1] / n_nodes;       // 5000
    if (n_nodes > MAX_N) n_nodes = MAX_N;
    if (n_edges > MAX_E) n_edges = MAX_E;

    int zmax = n_nodes > n_edges ? n_nodes : n_edges;
    zero_counts<<<(zmax + 255) / 256, 256>>>(n_nodes, n_edges);
    build_sparse<<<n_nodes, 256>>>(H, n_edges);
    gather_S<<<n_edges, FT>>>(X);
    gemm_M<<<(n_edges + 15) / 16, FT>>>(Wt, n_edges);
    scatter_out<<<n_nodes, FT>>>(bs, out);
}

// round 2
// speedup vs baseline: 1.2741x; 1.2741x over previous
#include <cuda_runtime.h>
#include <cuda_fp16.h>

#define MAX_N 20000
#define MAX_E 5000
#define FT 128
#define NODE_CAP 128   // max edges per node (mean ~50, 11 sigma headroom)
#define EDGE_CAP 384   // max nodes per edge (mean ~200, 13 sigma headroom)

// ---- scratch (__device__ globals; no allocations allowed) ----
__device__ int    g_dv[MAX_N];               // node degree
__device__ int    g_de[MAX_E];               // edge degree
__device__ int    g_csr[MAX_N * NODE_CAP];   // edges per node
__device__ int    g_csc[MAX_E * EDGE_CAP];   // nodes per edge
__device__ __align__(16) __half g_Xh[MAX_N * FT];  // X in fp16
__device__ __align__(16) __half g_Mh[MAX_E * FT];  // M in fp16

// ---------------------------------------------------------------------------
__global__ void zero_counts(int n_nodes, int n_edges) {
    int i = blockIdx.x * blockDim.x + threadIdx.x;
    if (i < n_nodes) g_dv[i] = 0;
    if (i < n_edges) g_de[i] = 0;
}

// X fp32 -> fp16 (10MB read, 5MB write; ~3us)
__global__ void convert_X(const float* __restrict__ X, int total4) {
    int i = blockIdx.x * blockDim.x + threadIdx.x;
    if (i < total4) {
        float4 v = ((const float4*)X)[i];
        __half2 a = __floats2half2_rn(v.x, v.y);
        __half2 b = __floats2half2_rn(v.z, v.w);
        uint2 p;
        p.x = *(unsigned*)&a;
        p.y = *(unsigned*)&b;
        ((uint2*)g_Xh)[i] = p;
    }
}

// One block per node row of H. Reads the whole 400MB of H exactly once,
// building CSR + CSC + degrees. HBM-bound (~65us floor).
__global__ __launch_bounds__(256) void build_sparse(const float* __restrict__ H,
                                                    int n_edges) {
    int n = blockIdx.x;
    __shared__ int s_cnt;
    if (threadIdx.x == 0) s_cnt = 0;
    __syncthreads();

    const float4* row = (const float4*)(H + (size_t)n * n_edges);
    int nq = n_edges >> 2;
    for (int i = threadIdx.x; i < nq; i += blockDim.x) {
        float4 v = row[i];
        int e0 = i << 2;
        int cnt = (v.x != 0.f) + (v.y != 0.f) + (v.z != 0.f) + (v.w != 0.f);
        if (cnt) {
            int pos = atomicAdd(&s_cnt, cnt);
            int es[4]; int k = 0;
            if (v.x != 0.f) es[k++] = e0;
            if (v.y != 0.f) es[k++] = e0 + 1;
            if (v.z != 0.f) es[k++] = e0 + 2;
            if (v.w != 0.f) es[k++] = e0 + 3;
            #pragma unroll
            for (int j = 0; j < 4; j++) {
                if (j >= k) break;
                int p = pos + j;
                if (p < NODE_CAP) g_csr[n * NODE_CAP + p] = es[j];
                int q = atomicAdd(&g_de[es[j]], 1);
                if (q < EDGE_CAP) g_csc[es[j] * EDGE_CAP + q] = n;
            }
        }
    }
    __syncthreads();
    if (threadIdx.x == 0) g_dv[n] = min(s_cnt, NODE_CAP);
}

// Fused: S[e] = sum_{n in edge e} X[n]  (fp16 rows, fp32 acc), then
// M[e][j] = (S[e] . W[:,j]) / de[e], stored fp16.
// 128 threads: warp g handles nodes[i+g], lane loads 4 features (8B).
__global__ __launch_bounds__(FT) void gather_gemm(const float* __restrict__ W) {
    int e = blockIdx.x;
    int t = threadIdx.x;
    int lane = t & 31;
    int g = t >> 5;
    int de = g_de[e];
    int cnt = min(de, EDGE_CAP);
    const int* __restrict__ nodes = g_csc + e * EDGE_CAP;

    float4 acc = make_float4(0.f, 0.f, 0.f, 0.f);
    for (int i = g; i < cnt; i += 4) {
        int n = nodes[i];
        uint2 p = ((const uint2*)(g_Xh + (size_t)n * FT))[lane];
        __half2 h0 = *(__half2*)&p.x;
        __half2 h1 = *(__half2*)&p.y;
        float2 f0 = __half22float2(h0);
        float2 f1 = __half22float2(h1);
        acc.x += f0.x; acc.y += f0.y; acc.z += f1.x; acc.w += f1.y;
    }

    __shared__ float part[4][FT];
    __shared__ float s[FT];
    ((float4*)part[g])[lane] = acc;
    __syncthreads();
    s[t] = (part[0][t] + part[1][t]) + (part[2][t] + part[3][t]);
    __syncthreads();

    // matvec: M[e][t] = (s . W[:,t]) / de ; 4 accumulators for ILP
    float a0 = 0.f, a1 = 0.f, a2 = 0.f, a3 = 0.f;
    #pragma unroll
    for (int k = 0; k < FT; k += 4) {
        a0 += s[k + 0] * W[(k + 0) * FT + t];
        a1 += s[k + 1] * W[(k + 1) * FT + t];
        a2 += s[k + 2] * W[(k + 2) * FT + t];
        a3 += s[k + 3] * W[(k + 3) * FT + t];
    }
    float a = (a0 + a1) + (a2 + a3);
    float m = (de > 0) ? a / (float)de : 0.f;
    g_Mh[e * FT + t] = __float2half(m);
}

// out[n] = relu( (sum_{e in node n} M[e]) / dv[n] + bias ).  Same layout trick.
__global__ __launch_bounds__(FT) void scatter_out(const float* __restrict__ bias,
                                                  float* __restrict__ out) {
    int n = blockIdx.x;
    int t = threadIdx.x;
    int lane = t & 31;
    int g = t >> 5;
    int cnt = g_dv[n];
    const int* __restrict__ edges = g_csr + n * NODE_CAP;

    float4 acc = make_float4(0.f, 0.f, 0.f, 0.f);
    for (int i = g; i < cnt; i += 4) {
        int e = edges[i];
        uint2 p = ((const uint2*)(g_Mh + (size_t)e * FT))[lane];
        __half2 h0 = *(__half2*)&p.x;
        __half2 h1 = *(__half2*)&p.y;
        float2 f0 = __half22float2(h0);
        float2 f1 = __half22float2(h1);
        acc.x += f0.x; acc.y += f0.y; acc.z += f1.x; acc.w += f1.y;
    }

    __shared__ float part[4][FT];
    ((float4*)part[g])[lane] = acc;
    __syncthreads();
    float v = (part[0][t] + part[1][t]) + (part[2][t] + part[3][t]);
    v = (cnt > 0) ? v / (float)cnt : 0.f;
    v += bias[t];
    out[(size_t)n * FT + t] = v > 0.f ? v : 0.f;
}

// ---------------------------------------------------------------------------
extern "C" void kernel_launch(void* const* d_in, const int* in_sizes, int n_in,
                              void* d_out, int out_size) {
    const float* X  = (const float*)d_in[0];   // [N, 128]
    const float* H  = (const float*)d_in[1];   // [N, E]
    const float* Wt = (const float*)d_in[2];   // [128, 128]
    const float* bs = (const float*)d_in[3];   // [128]
    float* out = (float*)d_out;                // [N, 128]

    int n_nodes = in_sizes[0] / FT;            // 20000
    int n_edges = in_sizes[1] / n_nodes;       // 5000
    if (n_nodes > MAX_N) n_nodes = MAX_N;
    if (n_edges > MAX_E) n_edges = MAX_E;

    int zmax = n_nodes > n_edges ? n_nodes : n_edges;
    zero_counts<<<(zmax + 255) / 256, 256>>>(n_nodes, n_edges);
    int total4 = n_nodes * FT / 4;
    convert_X<<<(total4 + 255) / 256, 256>>>(X, total4);
    build_sparse<<<n_nodes, 256>>>(H, n_edges);
    gather_gemm<<<n_edges, FT>>>(Wt);
    scatter_out<<<n_nodes, FT>>>(bs, out);
}

// round 3
// speedup vs baseline: 1.3658x; 1.0720x over previous
#include <cuda_runtime.h>
#include <cuda_fp16.h>
#include <mma.h>
using namespace nvcuda;

#define MAX_N 20000
#define MAX_E 5000
#define FT 128
#define NODE_CAP 128   // max edges per node (mean ~50, 11 sigma headroom)
#define EDGE_CAP 384   // max nodes per edge (mean ~200, 13 sigma headroom)
#define EPB 16         // edges per block in gather_mma

// ---- scratch (__device__ globals; no allocations allowed) ----
__device__ int    g_dv[MAX_N];               // node degree
__device__ int    g_de[MAX_E];               // edge degree
__device__ int    g_csr[MAX_N * NODE_CAP];   // edges per node
__device__ int    g_csc[MAX_E * EDGE_CAP];   // nodes per edge
__device__ __align__(16) __half g_Xh[MAX_N * FT];  // X in fp16
__device__ __align__(16) __half g_Wh[FT * FT];     // W in fp16 (row-major, k-major)
__device__ __align__(16) __half g_Mh[MAX_E * FT];  // M in fp16

// ---------------------------------------------------------------------------
__global__ void zero_counts(int n_nodes, int n_edges) {
    int i = blockIdx.x * blockDim.x + threadIdx.x;
    if (i < n_nodes) g_dv[i] = 0;
    if (i < n_edges) g_de[i] = 0;
}

// X and W fp32 -> fp16
__global__ void convert_XW(const float* __restrict__ X,
                           const float* __restrict__ W,
                           int x4, int w4) {
    int i = blockIdx.x * blockDim.x + threadIdx.x;
    if (i < x4) {
        float4 v = ((const float4*)X)[i];
        __half2 a = __floats2half2_rn(v.x, v.y);
        __half2 b = __floats2half2_rn(v.z, v.w);
        uint2 p; p.x = *(unsigned*)&a; p.y = *(unsigned*)&b;
        ((uint2*)g_Xh)[i] = p;
    } else if (i < x4 + w4) {
        int j = i - x4;
        float4 v = ((const float4*)W)[j];
        __half2 a = __floats2half2_rn(v.x, v.y);
        __half2 b = __floats2half2_rn(v.z, v.w);
        uint2 p; p.x = *(unsigned*)&a; p.y = *(unsigned*)&b;
        ((uint2*)g_Wh)[j] = p;
    }
}

// One block per node row of H. Reads the whole 400MB of H exactly once
// (streaming loads: don't pollute L2 needed for Xh later), building
// CSR + CSC + degrees. HBM-bound (~65us floor).
__global__ __launch_bounds__(256) void build_sparse(const float* __restrict__ H,
                                                    int n_edges) {
    int n = blockIdx.x;
    __shared__ int s_cnt;
    if (threadIdx.x == 0) s_cnt = 0;
    __syncthreads();

    const float4* row = (const float4*)(H + (size_t)n * n_edges);
    int nq = n_edges >> 2;
    for (int i = threadIdx.x; i < nq; i += blockDim.x) {
        float4 v = __ldcs(&row[i]);
        int e0 = i << 2;
        int cnt = (v.x != 0.f) + (v.y != 0.f) + (v.z != 0.f) + (v.w != 0.f);
        if (cnt) {
            int pos = atomicAdd(&s_cnt, cnt);
            int es[4]; int k = 0;
            if (v.x != 0.f) es[k++] = e0;
            if (v.y != 0.f) es[k++] = e0 + 1;
            if (v.z != 0.f) es[k++] = e0 + 2;
            if (v.w != 0.f) es[k++] = e0 + 3;
            #pragma unroll
            for (int j = 0; j < 4; j++) {
                if (j >= k) break;
                int p = pos + j;
                if (p < NODE_CAP) g_csr[n * NODE_CAP + p] = es[j];
                int q = atomicAdd(&g_de[es[j]], 1);
                if (q < EDGE_CAP) g_csc[es[j] * EDGE_CAP + q] = n;
            }
        }
    }
    __syncthreads();
    if (threadIdx.x == 0) g_dv[n] = min(s_cnt, NODE_CAP);
}

// 16 edges per block. Phase 1: warp w gathers S[w] = sum of X rows of edge
// e0+w (fp16 rows, fp32 acc, 2 nodes per warp-iter via uint4). Phase 2:
// 8 warps project the [16,128] S tile through W with HMMA (fp32 accum).
// Phase 3: epilogue divides by DE and stores M fp16.
__global__ __launch_bounds__(512) void gather_mma(int n_edges) {
    __shared__ __half s_h[EPB][FT];     // S tile, fp16
    __shared__ float  s_C[EPB][FT];     // C tile, fp32

    int w = threadIdx.x >> 5;
    int lane = threadIdx.x & 31;
    int e0 = blockIdx.x * EPB;
    int e = e0 + w;

    // ---- phase 1: gather ----
    int hw = lane >> 4;        // half-warp: 0/1 -> node parity
    int fl = lane & 15;        // feature-lane: features 8*fl .. 8*fl+7
    if (e < n_edges) {
        int cnt = min(g_de[e], EDGE_CAP);
        const int* __restrict__ nodes = g_csc + e * EDGE_CAP;
        float acc[8];
        #pragma unroll
        for (int j = 0; j < 8; j++) acc[j] = 0.f;
        for (int i = hw; i < cnt; i += 2) {
            int n = nodes[i];
            uint4 p = ((const uint4*)(g_Xh + (size_t)n * FT))[fl];
            __half2* hp = (__half2*)&p;
            #pragma unroll
            for (int q = 0; q < 4; q++) {
                float2 f = __half22float2(hp[q]);
                acc[2 * q]     += f.x;
                acc[2 * q + 1] += f.y;
            }
        }
        // combine the two half-warps (same features, different node subsets)
        #pragma unroll
        for (int j = 0; j < 8; j++)
            acc[j] += __shfl_xor_sync(0xffffffffu, acc[j], 16);
        if (hw == 0) {
            uint4 o;
            __half2 h0 = __floats2half2_rn(acc[0], acc[1]);
            __half2 h1 = __floats2half2_rn(acc[2], acc[3]);
            __half2 h2 = __floats2half2_rn(acc[4], acc[5]);
            __half2 h3 = __floats2half2_rn(acc[6], acc[7]);
            o.x = *(unsigned*)&h0; o.y = *(unsigned*)&h1;
            o.z = *(unsigned*)&h2; o.w = *(unsigned*)&h3;
            ((uint4*)&s_h[w][0])[fl] = o;
        }
    } else {
        if (lane < 16) ((uint4*)&s_h[w][0])[lane] = make_uint4(0, 0, 0, 0);
    }
    __syncthreads();

    // ---- phase 2: [16,128] x [128,128] HMMA, warp w handles n-tile w ----
    if (w < 8) {
        wmma::fragment<wmma::accumulator, 16, 16, 16, float> c;
        wmma::fill_fragment(c, 0.f);
        #pragma unroll
        for (int k = 0; k < FT; k += 16) {
            wmma::fragment<wmma::matrix_a, 16, 16, 16, __half, wmma::row_major> a;
            wmma::fragment<wmma::matrix_b, 16, 16, 16, __half, wmma::row_major> b;
            wmma::load_matrix_sync(a, &s_h[0][k], FT);
            wmma::load_matrix_sync(b, g_Wh + k * FT + w * 16, FT);
            wmma::mma_sync(c, a, b, c);
        }
        wmma::store_matrix_sync(&s_C[0][w * 16], c, FT, wmma::mem_row_major);
    }
    __syncthreads();

    // ---- phase 3: epilogue M = C / DE ----
    for (int idx = threadIdx.x; idx < EPB * FT; idx += 512) {
        int r = idx >> 7, j = idx & (FT - 1);
        int e2 = e0 + r;
        if (e2 < n_edges) {
            int de = g_de[e2];
            float m = (de > 0) ? s_C[r][j] / (float)de : 0.f;
            g_Mh[(size_t)e2 * FT + j] = __float2half(m);
        }
    }
}

// out[n] = relu( (sum_{e in node n} M[e]) / dv[n] + bias ).
__global__ __launch_bounds__(FT) void scatter_out(const float* __restrict__ bias,
                                                  float* __restrict__ out) {
    int n = blockIdx.x;
    int t = threadIdx.x;
    int lane = t & 31;
    int g = t >> 5;
    int cnt = g_dv[n];
    const int* __restrict__ edges = g_csr + n * NODE_CAP;

    float4 acc = make_float4(0.f, 0.f, 0.f, 0.f);
    for (int i = g; i < cnt; i += 4) {
        int e = edges[i];
        uint2 p = ((const uint2*)(g_Mh + (size_t)e * FT))[lane];
        __half2 h0 = *(__half2*)&p.x;
        __half2 h1 = *(__half2*)&p.y;
        float2 f0 = __half22float2(h0);
        float2 f1 = __half22float2(h1);
        acc.x += f0.x; acc.y += f0.y; acc.z += f1.x; acc.w += f1.y;
    }

    __shared__ float part[4][FT];
    ((float4*)part[g])[lane] = acc;
    __syncthreads();
    float v = (part[0][t] + part[1][t]) + (part[2][t] + part[3][t]);
    v = (cnt > 0) ? v / (float)cnt : 0.f;
    v += bias[t];
    out[(size_t)n * FT + t] = v > 0.f ? v : 0.f;
}

// ---------------------------------------------------------------------------
extern "C" void kernel_launch(void* const* d_in, const int* in_sizes, int n_in,
                              void* d_out, int out_size) {
    const float* X  = (const float*)d_in[0];   // [N, 128]
    const float* H  = (const float*)d_in[1];   // [N, E]
    const float* Wt = (const float*)d_in[2];   // [128, 128]
    const float* bs = (const float*)d_in[3];   // [128]
    float* out = (float*)d_out;                // [N, 128]

    int n_nodes = in_sizes[0] / FT;            // 20000
    int n_edges = in_sizes[1] / n_nodes;       // 5000
    if (n_nodes > MAX_N) n_nodes = MAX_N;
    if (n_edges > MAX_E) n_edges = MAX_E;

    int zmax = n_nodes > n_edges ? n_nodes : n_edges;
    zero_counts<<<(zmax + 255) / 256, 256>>>(n_nodes, n_edges);
    int x4 = n_nodes * FT / 4;
    int w4 = FT * FT / 4;
    convert_XW<<<(x4 + w4 + 255) / 256, 256>>>(X, Wt, x4, w4);
    build_sparse<<<n_nodes, 256>>>(H, n_edges);
    gather_mma<<<(n_edges + EPB - 1) / EPB, 512>>>(n_edges);
    scatter_out<<<n_nodes, FT>>>(bs, out);
}

// round 4
// speedup vs baseline: 1.3835x; 1.0129x over previous
#include <cuda_runtime.h>
#include <cuda_fp16.h>
#include <mma.h>
using namespace nvcuda;

#define MAX_N 20000
#define MAX_E 5000
#define FT 128
#define NODE_CAP 128   // max edges per node (mean ~50, 11 sigma headroom)
#define EDGE_CAP 384   // max nodes per edge (mean ~200, 13 sigma headroom)
#define EPB 16         // edges per block in gather_mma

// ---- scratch (__device__ globals; no allocations allowed) ----
__device__ int    g_dv[MAX_N];               // node degree
__device__ int    g_de[MAX_E];               // edge degree
__device__ int    g_csr[MAX_N * NODE_CAP];   // edges per node
__device__ int    g_csc[MAX_E * EDGE_CAP];   // nodes per edge
__device__ __align__(16) __half g_Xh[MAX_N * FT];  // X in fp16
__device__ __align__(16) __half g_Wh[FT * FT];     // W in fp16
__device__ __align__(16) __half g_Mh[MAX_E * FT];  // M in fp16

// ---------------------------------------------------------------------------
// Fused: zero degree counters + convert X and W to fp16.
__global__ void prep(const float* __restrict__ X, const float* __restrict__ W,
                     int x4, int w4, int n_nodes, int n_edges) {
    int i = blockIdx.x * blockDim.x + threadIdx.x;
    if (i < n_nodes) g_dv[i] = 0;
    if (i < n_edges) g_de[i] = 0;
    if (i < x4) {
        float4 v = ((const float4*)X)[i];
        __half2 a = __floats2half2_rn(v.x, v.y);
        __half2 b = __floats2half2_rn(v.z, v.w);
        uint2 p; p.x = *(unsigned*)&a; p.y = *(unsigned*)&b;
        ((uint2*)g_Xh)[i] = p;
    } else if (i < x4 + w4) {
        int j = i - x4;
        float4 v = ((const float4*)W)[j];
        __half2 a = __floats2half2_rn(v.x, v.y);
        __half2 b = __floats2half2_rn(v.z, v.w);
        uint2 p; p.x = *(unsigned*)&a; p.y = *(unsigned*)&b;
        ((uint2*)g_Wh)[j] = p;
    }
}

// One block per node row of H. Reads the whole 400MB of H exactly once
// (streaming loads), building CSR + CSC + degrees. HBM-bound (~65us floor).
__global__ __launch_bounds__(256) void build_sparse(const float* __restrict__ H,
                                                    int n_edges) {
    int n = blockIdx.x;
    __shared__ int s_cnt;
    if (threadIdx.x == 0) s_cnt = 0;
    __syncthreads();

    const float4* row = (const float4*)(H + (size_t)n * n_edges);
    int nq = n_edges >> 2;
    for (int i = threadIdx.x; i < nq; i += blockDim.x) {
        float4 v = __ldcs(&row[i]);
        int e0 = i << 2;
        int cnt = (v.x != 0.f) + (v.y != 0.f) + (v.z != 0.f) + (v.w != 0.f);
        if (cnt) {
            int pos = atomicAdd(&s_cnt, cnt);
            int es[4]; int k = 0;
            if (v.x != 0.f) es[k++] = e0;
            if (v.y != 0.f) es[k++] = e0 + 1;
            if (v.z != 0.f) es[k++] = e0 + 2;
            if (v.w != 0.f) es[k++] = e0 + 3;
            #pragma unroll
            for (int j = 0; j < 4; j++) {
                if (j >= k) break;
                int p = pos + j;
                if (p < NODE_CAP) g_csr[n * NODE_CAP + p] = es[j];
                int q = atomicAdd(&g_de[es[j]], 1);
                if (q < EDGE_CAP) g_csc[es[j] * EDGE_CAP + q] = n;
            }
        }
    }
    __syncthreads();
    if (threadIdx.x == 0) g_dv[n] = min(s_cnt, NODE_CAP);
}

// 16 edges per block. Phase 1: warp w gathers S[w] with 4 independent
// LDG.128 in flight per lane (MLP=4). Phase 2: 8 warps project the [16,128]
// S tile through W with HMMA. Phase 3: epilogue divides by DE, stores fp16.
__global__ __launch_bounds__(512) void gather_mma(int n_edges) {
    __shared__ __half s_h[EPB][FT];
    __shared__ float  s_C[EPB][FT];

    int w = threadIdx.x >> 5;
    int lane = threadIdx.x & 31;
    int e0 = blockIdx.x * EPB;
    int e = e0 + w;

    // ---- phase 1: gather ----
    int hw = lane >> 4;        // half-warp -> node parity
    int fl = lane & 15;        // feature lane: 8 features
    if (e < n_edges) {
        int cnt = min(g_de[e], EDGE_CAP);
        const int* __restrict__ nodes = g_csc + e * EDGE_CAP;
        float acc[8];
        #pragma unroll
        for (int j = 0; j < 8; j++) acc[j] = 0.f;

        int i = hw;
        for (; i + 8 <= cnt; i += 8) {   // 4 nodes per half-warp per iter
            int n0 = nodes[i];
            int n1 = nodes[i + 2];
            int n2 = nodes[i + 4];
            int n3 = nodes[i + 6];
            uint4 p0 = ((const uint4*)(g_Xh + (size_t)n0 * FT))[fl];
            uint4 p1 = ((const uint4*)(g_Xh + (size_t)n1 * FT))[fl];
            uint4 p2 = ((const uint4*)(g_Xh + (size_t)n2 * FT))[fl];
            uint4 p3 = ((const uint4*)(g_Xh + (size_t)n3 * FT))[fl];
            __half2* h0 = (__half2*)&p0;
            __half2* h1 = (__half2*)&p1;
            __half2* h2 = (__half2*)&p2;
            __half2* h3 = (__half2*)&p3;
            #pragma unroll
            for (int q = 0; q < 4; q++) {
                float2 f0 = __half22float2(h0[q]);
                float2 f1 = __half22float2(h1[q]);
                float2 f2 = __half22float2(h2[q]);
                float2 f3 = __half22float2(h3[q]);
                acc[2 * q]     += (f0.x + f1.x) + (f2.x + f3.x);
                acc[2 * q + 1] += (f0.y + f1.y) + (f2.y + f3.y);
            }
        }
        for (; i < cnt; i += 2) {
            int n = nodes[i];
            uint4 p = ((const uint4*)(g_Xh + (size_t)n * FT))[fl];
            __half2* hp = (__half2*)&p;
            #pragma unroll
            for (int q = 0; q < 4; q++) {
                float2 f = __half22float2(hp[q]);
                acc[2 * q]     += f.x;
                acc[2 * q + 1] += f.y;
            }
        }
        #pragma unroll
        for (int j = 0; j < 8; j++)
            acc[j] += __shfl_xor_sync(0xffffffffu, acc[j], 16);
        if (hw == 0) {
            uint4 o;
            __half2 h0 = __floats2half2_rn(acc[0], acc[1]);
            __half2 h1 = __floats2half2_rn(acc[2], acc[3]);
            __half2 h2 = __floats2half2_rn(acc[4], acc[5]);
            __half2 h3 = __floats2half2_rn(acc[6], acc[7]);
            o.x = *(unsigned*)&h0; o.y = *(unsigned*)&h1;
            o.z = *(unsigned*)&h2; o.w = *(unsigned*)&h3;
            ((uint4*)&s_h[w][0])[fl] = o;
        }
    } else {
        if (lane < 16) ((uint4*)&s_h[w][0])[lane] = make_uint4(0, 0, 0, 0);
    }
    __syncthreads();

    // ---- phase 2: [16,128] x [128,128] HMMA ----
    if (w < 8) {
        wmma::fragment<wmma::accumulator, 16, 16, 16, float> c;
        wmma::fill_fragment(c, 0.f);
        #pragma unroll
        for (int k = 0; k < FT; k += 16) {
            wmma::fragment<wmma::matrix_a, 16, 16, 16, __half, wmma::row_major> a;
            wmma::fragment<wmma::matrix_b, 16, 16, 16, __half, wmma::row_major> b;
            wmma::load_matrix_sync(a, &s_h[0][k], FT);
            wmma::load_matrix_sync(b, g_Wh + k * FT + w * 16, FT);
            wmma::mma_sync(c, a, b, c);
        }
        wmma::store_matrix_sync(&s_C[0][w * 16], c, FT, wmma::mem_row_major);
    }
    __syncthreads();

    // ---- phase 3: epilogue M = C / DE ----
    for (int idx = threadIdx.x; idx < EPB * FT; idx += 512) {
        int r = idx >> 7, j = idx & (FT - 1);
        int e2 = e0 + r;
        if (e2 < n_edges) {
            int de = g_de[e2];
            float m = (de > 0) ? s_C[r][j] / (float)de : 0.f;
            g_Mh[(size_t)e2 * FT + j] = __float2half(m);
        }
    }
}

// out[n] = relu( (sum_{e in node n} M[e]) / dv[n] + bias ).
// Warp-group g handles edges i = g, g+4, ...; unrolled x4 for MLP=4.
__global__ __launch_bounds__(FT) void scatter_out(const float* __restrict__ bias,
                                                  float* __restrict__ out) {
    int n = blockIdx.x;
    int t = threadIdx.x;
    int lane = t & 31;
    int g = t >> 5;
    int cnt = g_dv[n];
    const int* __restrict__ edges = g_csr + n * NODE_CAP;

    float4 acc = make_float4(0.f, 0.f, 0.f, 0.f);
    int i = g;
    for (; i + 16 <= cnt; i += 16) {   // 4 edges per group per iter
        int e0 = edges[i];
        int e1 = edges[i + 4];
        int e2 = edges[i + 8];
        int e3 = edges[i + 12];
        uint2 p0 = ((const uint2*)(g_Mh + (size_t)e0 * FT))[lane];
        uint2 p1 = ((const uint2*)(g_Mh + (size_t)e1 * FT))[lane];
        uint2 p2 = ((const uint2*)(g_Mh + (size_t)e2 * FT))[lane];
        uint2 p3 = ((const uint2*)(g_Mh + (size_t)e3 * FT))[lane];
        float2 a0 = __half22float2(*(__half2*)&p0.x), b0 = __half22float2(*(__half2*)&p0.y);
        float2 a1 = __half22float2(*(__half2*)&p1.x), b1 = __half22float2(*(__half2*)&p1.y);
        float2 a2 = __half22float2(*(__half2*)&p2.x), b2 = __half22float2(*(__half2*)&p2.y);
        float2 a3 = __half22float2(*(__half2*)&p3.x), b3 = __half22float2(*(__half2*)&p3.y);
        acc.x += (a0.x + a1.x) + (a2.x + a3.x);
        acc.y += (a0.y + a1.y) + (a2.y + a3.y);
        acc.z += (b0.x + b1.x) + (b2.x + b3.x);
        acc.w += (b0.y + b1.y) + (b2.y + b3.y);
    }
    for (; i < cnt; i += 4) {
        int e = edges[i];
        uint2 p = ((const uint2*)(g_Mh + (size_t)e * FT))[lane];
        float2 f0 = __half22float2(*(__half2*)&p.x);
        float2 f1 = __half22float2(*(__half2*)&p.y);
        acc.x += f0.x; acc.y += f0.y; acc.z += f1.x; acc.w += f1.y;
    }

    __shared__ float part[4][FT];
    ((float4*)part[g])[lane] = acc;
    __syncthreads();
    float v = (part[0][t] + part[1][t]) + (part[2][t] + part[3][t]);
    v = (cnt > 0) ? v / (float)cnt : 0.f;
    v += bias[t];
    out[(size_t)n * FT + t] = v > 0.f ? v : 0.f;
}

// ---------------------------------------------------------------------------
extern "C" void kernel_launch(void* const* d_in, const int* in_sizes, int n_in,
                              void* d_out, int out_size) {
    const float* X  = (const float*)d_in[0];   // [N, 128]
    const float* H  = (const float*)d_in[1];   // [N, E]
    const float* Wt = (const float*)d_in[2];   // [128, 128]
    const float* bs = (const float*)d_in[3];   // [128]
    float* out = (float*)d_out;                // [N, 128]

    int n_nodes = in_sizes[0] / FT;            // 20000
    int n_edges = in_sizes[1] / n_nodes;       // 5000
    if (n_nodes > MAX_N) n_nodes = MAX_N;
    if (n_edges > MAX_E) n_edges = MAX_E;

    int x4 = n_nodes * FT / 4;
    int w4 = FT * FT / 4;
    int ptot = x4 + w4;
    if (n_nodes > ptot) ptot = n_nodes;
    prep<<<(ptot + 255) / 256, 256>>>(X, Wt, x4, w4, n_nodes, n_edges);
    build_sparse<<<n_nodes, 256>>>(H, n_edges);
    gather_mma<<<(n_edges + EPB - 1) / EPB, 512>>>(n_edges);
    scatter_out<<<n_nodes, FT>>>(bs, out);
}

// round 5
// speedup vs baseline: 1.4042x; 1.0150x over previous
#include <cuda_runtime.h>
#include <cuda_fp16.h>
#include <mma.h>
using namespace nvcuda;

#define MAX_N 20000
#define MAX_E 5000
#define FT 128
#define NODE_CAP 128   // max edges per node (mean ~50, 11 sigma headroom)
#define EDGE_CAP 384   // max nodes per edge (mean ~200, 13 sigma headroom)
#define EPB 16         // edges per block in gather_mma

// ---- scratch (__device__ globals; no allocations allowed) ----
__device__ int    g_dv[MAX_N];               // node degree
__device__ int    g_de[MAX_E];               // edge degree
__device__ int    g_csr[MAX_N * NODE_CAP];   // edges per node
__device__ int    g_csc[MAX_E * EDGE_CAP];   // nodes per edge
__device__ __align__(16) __half g_Xh[MAX_N * FT];  // X in fp16
__device__ __align__(16) __half g_Wh[FT * FT];     // W in fp16
__device__ __align__(16) __half g_Mh[MAX_E * FT];  // M in fp16

// ---------------------------------------------------------------------------
// Fused: zero degree counters + convert X and W to fp16.
__global__ void prep(const float* __restrict__ X, const float* __restrict__ W,
                     int x4, int w4, int n_nodes, int n_edges) {
    int i = blockIdx.x * blockDim.x + threadIdx.x;
    if (i < n_nodes) g_dv[i] = 0;
    if (i < n_edges) g_de[i] = 0;
    if (i < x4) {
        float4 v = ((const float4*)X)[i];
        __half2 a = __floats2half2_rn(v.x, v.y);
        __half2 b = __floats2half2_rn(v.z, v.w);
        uint2 p; p.x = *(unsigned*)&a; p.y = *(unsigned*)&b;
        ((uint2*)g_Xh)[i] = p;
    } else if (i < x4 + w4) {
        int j = i - x4;
        float4 v = ((const float4*)W)[j];
        __half2 a = __floats2half2_rn(v.x, v.y);
        __half2 b = __floats2half2_rn(v.z, v.w);
        uint2 p; p.x = *(unsigned*)&a; p.y = *(unsigned*)&b;
        ((uint2*)g_Wh)[j] = p;
    }
}

// Process one float4 quad of an H row: record nonzero edges.
__device__ __forceinline__ void proc_quad(float4 v, int e0, int n, int* s_cnt) {
    int cnt = (v.x != 0.f) + (v.y != 0.f) + (v.z != 0.f) + (v.w != 0.f);
    if (cnt) {
        int pos = atomicAdd(s_cnt, cnt);
        int es[4]; int k = 0;
        if (v.x != 0.f) es[k++] = e0;
        if (v.y != 0.f) es[k++] = e0 + 1;
        if (v.z != 0.f) es[k++] = e0 + 2;
        if (v.w != 0.f) es[k++] = e0 + 3;
        #pragma unroll
        for (int j = 0; j < 4; j++) {
            if (j >= k) break;
            int p = pos + j;
            if (p < NODE_CAP) g_csr[n * NODE_CAP + p] = es[j];
            int q = atomicAdd(&g_de[es[j]], 1);
            if (q < EDGE_CAP) g_csc[es[j] * EDGE_CAP + q] = n;
        }
    }
}

// One block per node row of H; reads all 400MB exactly once (streaming),
// two independent float4 streams per thread for DRAM MLP.
__global__ __launch_bounds__(256, 8) void build_sparse(const float* __restrict__ H,
                                                       int n_edges) {
    int n = blockIdx.x;
    __shared__ int s_cnt;
    if (threadIdx.x == 0) s_cnt = 0;
    __syncthreads();

    const float4* row = (const float4*)(H + (size_t)n * n_edges);
    int nq = n_edges >> 2;
    for (int i = threadIdx.x; i < nq; i += 2 * blockDim.x) {
        int i2 = i + blockDim.x;
        float4 v0 = __ldcs(&row[i]);
        float4 v1;
        bool has1 = (i2 < nq);
        if (has1) v1 = __ldcs(&row[i2]);
        proc_quad(v0, i << 2, n, &s_cnt);
        if (has1) proc_quad(v1, i2 << 2, n, &s_cnt);
    }
    __syncthreads();
    if (threadIdx.x == 0) g_dv[n] = min(s_cnt, NODE_CAP);
}

// 16 edges per block. Phase 1: warp w gathers S[w] with 4 independent
// LDG.128 in flight per lane (launch_bounds(512,2) -> 64-reg budget so the
// MLP actually materializes). Phase 2: HMMA projection. Phase 3: /DE, fp16.
__global__ __launch_bounds__(512, 2) void gather_mma(int n_edges) {
    __shared__ __half s_h[EPB][FT];
    __shared__ float  s_C[EPB][FT];

    int w = threadIdx.x >> 5;
    int lane = threadIdx.x & 31;
    int e0 = blockIdx.x * EPB;
    int e = e0 + w;

    // ---- phase 1: gather ----
    int hw = lane >> 4;        // half-warp -> node parity
    int fl = lane & 15;        // feature lane: 8 features
    if (e < n_edges) {
        int cnt = min(g_de[e], EDGE_CAP);
        const int* __restrict__ nodes = g_csc + e * EDGE_CAP;
        float acc[8];
        #pragma unroll
        for (int j = 0; j < 8; j++) acc[j] = 0.f;

        int i = hw;
        for (; i + 8 <= cnt; i += 8) {   // 4 nodes per half-warp per iter
            int n0 = nodes[i];
            int n1 = nodes[i + 2];
            int n2 = nodes[i + 4];
            int n3 = nodes[i + 6];
            uint4 p0 = ((const uint4*)(g_Xh + (size_t)n0 * FT))[fl];
            uint4 p1 = ((const uint4*)(g_Xh + (size_t)n1 * FT))[fl];
            uint4 p2 = ((const uint4*)(g_Xh + (size_t)n2 * FT))[fl];
            uint4 p3 = ((const uint4*)(g_Xh + (size_t)n3 * FT))[fl];
            __half2* h0 = (__half2*)&p0;
            __half2* h1 = (__half2*)&p1;
            __half2* h2 = (__half2*)&p2;
            __half2* h3 = (__half2*)&p3;
            #pragma unroll
            for (int q = 0; q < 4; q++) {
                float2 f0 = __half22float2(h0[q]);
                float2 f1 = __half22float2(h1[q]);
                float2 f2 = __half22float2(h2[q]);
                float2 f3 = __half22float2(h3[q]);
                acc[2 * q]     += (f0.x + f1.x) + (f2.x + f3.x);
                acc[2 * q + 1] += (f0.y + f1.y) + (f2.y + f3.y);
            }
        }
        for (; i < cnt; i += 2) {
            int n = nodes[i];
            uint4 p = ((const uint4*)(g_Xh + (size_t)n * FT))[fl];
            __half2* hp = (__half2*)&p;
            #pragma unroll
            for (int q = 0; q < 4; q++) {
                float2 f = __half22float2(hp[q]);
                acc[2 * q]     += f.x;
                acc[2 * q + 1] += f.y;
            }
        }
        #pragma unroll
        for (int j = 0; j < 8; j++)
            acc[j] += __shfl_xor_sync(0xffffffffu, acc[j], 16);
        if (hw == 0) {
            uint4 o;
            __half2 h0 = __floats2half2_rn(acc[0], acc[1]);
            __half2 h1 = __floats2half2_rn(acc[2], acc[3]);
            __half2 h2 = __floats2half2_rn(acc[4], acc[5]);
            __half2 h3 = __floats2half2_rn(acc[6], acc[7]);
            o.x = *(unsigned*)&h0; o.y = *(unsigned*)&h1;
            o.z = *(unsigned*)&h2; o.w = *(unsigned*)&h3;
            ((uint4*)&s_h[w][0])[fl] = o;
        }
    } else {
        if (lane < 16) ((uint4*)&s_h[w][0])[lane] = make_uint4(0, 0, 0, 0);
    }
    __syncthreads();

    // ---- phase 2: [16,128] x [128,128] HMMA ----
    if (w < 8) {
        wmma::fragment<wmma::accumulator, 16, 16, 16, float> c;
        wmma::fill_fragment(c, 0.f);
        #pragma unroll
        for (int k = 0; k < FT; k += 16) {
            wmma::fragment<wmma::matrix_a, 16, 16, 16, __half, wmma::row_major> a;
            wmma::fragment<wmma::matrix_b, 16, 16, 16, __half, wmma::row_major> b;
            wmma::load_matrix_sync(a, &s_h[0][k], FT);
            wmma::load_matrix_sync(b, g_Wh + k * FT + w * 16, FT);
            wmma::mma_sync(c, a, b, c);
        }
        wmma::store_matrix_sync(&s_C[0][w * 16], c, FT, wmma::mem_row_major);
    }
    __syncthreads();

    // ---- phase 3: epilogue M = C / DE ----
    for (int idx = threadIdx.x; idx < EPB * FT; idx += 512) {
        int r = idx >> 7, j = idx & (FT - 1);
        int e2 = e0 + r;
        if (e2 < n_edges) {
            int de = g_de[e2];
            float m = (de > 0) ? s_C[r][j] / (float)de : 0.f;
            g_Mh[(size_t)e2 * FT + j] = __float2half(m);
        }
    }
}

// out[n] = relu( (sum_{e in node n} M[e]) / dv[n] + bias ).
// launch_bounds(128,8) -> 64-reg budget so the x4 unroll keeps MLP=4.
__global__ __launch_bounds__(FT, 8) void scatter_out(const float* __restrict__ bias,
                                                     float* __restrict__ out) {
    int n = blockIdx.x;
    int t = threadIdx.x;
    int lane = t & 31;
    int g = t >> 5;
    int cnt = g_dv[n];
    const int* __restrict__ edges = g_csr + n * NODE_CAP;

    float4 acc = make_float4(0.f, 0.f, 0.f, 0.f);
    int i = g;
    for (; i + 16 <= cnt; i += 16) {   // 4 edges per group per iter
        int e0 = edges[i];
        int e1 = edges[i + 4];
        int e2 = edges[i + 8];
        int e3 = edges[i + 12];
        uint2 p0 = ((const uint2*)(g_Mh + (size_t)e0 * FT))[lane];
        uint2 p1 = ((const uint2*)(g_Mh + (size_t)e1 * FT))[lane];
        uint2 p2 = ((const uint2*)(g_Mh + (size_t)e2 * FT))[lane];
        uint2 p3 = ((const uint2*)(g_Mh + (size_t)e3 * FT))[lane];
        float2 a0 = __half22float2(*(__half2*)&p0.x), b0 = __half22float2(*(__half2*)&p0.y);
        float2 a1 = __half22float2(*(__half2*)&p1.x), b1 = __half22float2(*(__half2*)&p1.y);
        float2 a2 = __half22float2(*(__half2*)&p2.x), b2 = __half22float2(*(__half2*)&p2.y);
        float2 a3 = __half22float2(*(__half2*)&p3.x), b3 = __half22float2(*(__half2*)&p3.y);
        acc.x += (a0.x + a1.x) + (a2.x + a3.x);
        acc.y += (a0.y + a1.y) + (a2.y + a3.y);
        acc.z += (b0.x + b1.x) + (b2.x + b3.x);
        acc.w += (b0.y + b1.y) + (b2.y + b3.y);
    }
    for (; i < cnt; i += 4) {
        int e = edges[i];
        uint2 p = ((const uint2*)(g_Mh + (size_t)e * FT))[lane];
        float2 f0 = __half22float2(*(__half2*)&p.x);
        float2 f1 = __half22float2(*(__half2*)&p.y);
        acc.x += f0.x; acc.y += f0.y; acc.z += f1.x; acc.w += f1.y;
    }

    __shared__ float part[4][FT];
    ((float4*)part[g])[lane] = acc;
    __syncthreads();
    float v = (part[0][t] + part[1][t]) + (part[2][t] + part[3][t]);
    v = (cnt > 0) ? v / (float)cnt : 0.f;
    v += bias[t];
    out[(size_t)n * FT + t] = v > 0.f ? v : 0.f;
}

// ---------------------------------------------------------------------------
extern "C" void kernel_launch(void* const* d_in, const int* in_sizes, int n_in,
                              void* d_out, int out_size) {
    const float* X  = (const float*)d_in[0];   // [N, 128]
    const float* H  = (const float*)d_in[1];   // [N, E]
    const float* Wt = (const float*)d_in[2];   // [128, 128]
    const float* bs = (const float*)d_in[3];   // [128]
    float* out = (float*)d_out;                // [N, 128]

    int n_nodes = in_sizes[0] / FT;            // 20000
    int n_edges = in_sizes[1] / n_nodes;       // 5000
    if (n_nodes > MAX_N) n_nodes = MAX_N;
    if (n_edges > MAX_E) n_edges = MAX_E;

    int x4 = n_nodes * FT / 4;
    int w4 = FT * FT / 4;
    int ptot = x4 + w4;
    if (n_nodes > ptot) ptot = n_nodes;
    prep<<<(ptot + 255) / 256, 256>>>(X, Wt, x4, w4, n_nodes, n_edges);
    build_sparse<<<n_nodes, 256>>>(H, n_edges);
    gather_mma<<<(n_edges + EPB - 1) / EPB, 512>>>(n_edges);
    scatter_out<<<n_nodes, FT>>>(bs, out);
}

// round 6
// speedup vs baseline: 1.4441x; 1.0285x over previous
#include <cuda_runtime.h>
#include <cuda_fp16.h>
#include <mma.h>
using namespace nvcuda;

#define MAX_N 20000
#define MAX_E 5000
#define FT 128
#define NODE_CAP 128   // max edges per node (mean ~50, 11 sigma headroom)
#define EDGE_CAP 384   // max nodes per edge (mean ~200, 13 sigma headroom)
#define EPB 16         // edges per block in gather_mma

// ---- scratch (__device__ globals; no allocations allowed) ----
__device__ int    g_dv[MAX_N];               // node degree
__device__ int    g_de[MAX_E];               // edge degree
__device__ int    g_csr[MAX_N * NODE_CAP];   // edges per node
__device__ int    g_csc[MAX_E * EDGE_CAP];   // nodes per edge
__device__ __align__(16) __half g_Xh[MAX_N * FT];  // X in fp16
__device__ __align__(16) __half g_Wh[FT * FT];     // W in fp16
__device__ __align__(16) __half g_Mh[MAX_E * FT];  // M in fp16

// ---------------------------------------------------------------------------
// Fused: zero degree counters + convert X and W to fp16.
__global__ void prep(const float* __restrict__ X, const float* __restrict__ W,
                     int x4, int w4, int n_nodes, int n_edges) {
    int i = blockIdx.x * blockDim.x + threadIdx.x;
    if (i < n_nodes) g_dv[i] = 0;
    if (i < n_edges) g_de[i] = 0;
    if (i < x4) {
        float4 v = ((const float4*)X)[i];
        __half2 a = __floats2half2_rn(v.x, v.y);
        __half2 b = __floats2half2_rn(v.z, v.w);
        uint2 p; p.x = *(unsigned*)&a; p.y = *(unsigned*)&b;
        ((uint2*)g_Xh)[i] = p;
    } else if (i < x4 + w4) {
        int j = i - x4;
        float4 v = ((const float4*)W)[j];
        __half2 a = __floats2half2_rn(v.x, v.y);
        __half2 b = __floats2half2_rn(v.z, v.w);
        uint2 p; p.x = *(unsigned*)&a; p.y = *(unsigned*)&b;
        ((uint2*)g_Wh)[j] = p;
    }
}

// Process one float4 quad of an H row: record nonzero edges.
__device__ __forceinline__ void proc_quad(float4 v, int e0, int n, int* s_cnt) {
    int cnt = (v.x != 0.f) + (v.y != 0.f) + (v.z != 0.f) + (v.w != 0.f);
    if (cnt) {
        int pos = atomicAdd(s_cnt, cnt);
        int es[4]; int k = 0;
        if (v.x != 0.f) es[k++] = e0;
        if (v.y != 0.f) es[k++] = e0 + 1;
        if (v.z != 0.f) es[k++] = e0 + 2;
        if (v.w != 0.f) es[k++] = e0 + 3;
        #pragma unroll
        for (int j = 0; j < 4; j++) {
            if (j >= k) break;
            int p = pos + j;
            if (p < NODE_CAP) g_csr[n * NODE_CAP + p] = es[j];
            int q = atomicAdd(&g_de[es[j]], 1);
            if (q < EDGE_CAP) g_csc[es[j] * EDGE_CAP + q] = n;
        }
    }
}

// One block per node row of H; reads all 400MB exactly once (streaming),
// FOUR independent float4 streams per thread for DRAM MLP.
__global__ __launch_bounds__(256, 8) void build_sparse(const float* __restrict__ H,
                                                       int n_edges) {
    int n = blockIdx.x;
    __shared__ int s_cnt;
    if (threadIdx.x == 0) s_cnt = 0;
    __syncthreads();

    const float4* row = (const float4*)(H + (size_t)n * n_edges);
    int nq = n_edges >> 2;
    for (int i0 = threadIdx.x; i0 < nq; i0 += 4 * blockDim.x) {
        int i1 = i0 + blockDim.x;
        int i2 = i0 + 2 * blockDim.x;
        int i3 = i0 + 3 * blockDim.x;
        float4 v0 = __ldcs(&row[i0]);
        float4 v1, v2, v3;
        bool h1 = (i1 < nq), h2 = (i2 < nq), h3 = (i3 < nq);
        if (h1) v1 = __ldcs(&row[i1]);
        if (h2) v2 = __ldcs(&row[i2]);
        if (h3) v3 = __ldcs(&row[i3]);
        proc_quad(v0, i0 << 2, n, &s_cnt);
        if (h1) proc_quad(v1, i1 << 2, n, &s_cnt);
        if (h2) proc_quad(v2, i2 << 2, n, &s_cnt);
        if (h3) proc_quad(v3, i3 << 2, n, &s_cnt);
    }
    __syncthreads();
    if (threadIdx.x == 0) g_dv[n] = min(s_cnt, NODE_CAP);
}

// 16 edges per block. Phase 1: warp w gathers S[w] with 4 independent
// LDG.128 in flight per lane (launch_bounds(512,2) -> 64-reg budget).
// Phase 2: HMMA projection. Phase 3: /DE, store fp16.
__global__ __launch_bounds__(512, 2) void gather_mma(int n_edges) {
    __shared__ __half s_h[EPB][FT];
    __shared__ float  s_C[EPB][FT];

    int w = threadIdx.x >> 5;
    int lane = threadIdx.x & 31;
    int e0 = blockIdx.x * EPB;
    int e = e0 + w;

    // ---- phase 1: gather ----
    int hw = lane >> 4;        // half-warp -> node parity
    int fl = lane & 15;        // feature lane: 8 features
    if (e < n_edges) {
        int cnt = min(g_de[e], EDGE_CAP);
        const int* __restrict__ nodes = g_csc + e * EDGE_CAP;
        float acc[8];
        #pragma unroll
        for (int j = 0; j < 8; j++) acc[j] = 0.f;

        int i = hw;
        for (; i + 8 <= cnt; i += 8) {   // 4 nodes per half-warp per iter
            int n0 = nodes[i];
            int n1 = nodes[i + 2];
            int n2 = nodes[i + 4];
            int n3 = nodes[i + 6];
            uint4 p0 = ((const uint4*)(g_Xh + (size_t)n0 * FT))[fl];
            uint4 p1 = ((const uint4*)(g_Xh + (size_t)n1 * FT))[fl];
            uint4 p2 = ((const uint4*)(g_Xh + (size_t)n2 * FT))[fl];
            uint4 p3 = ((const uint4*)(g_Xh + (size_t)n3 * FT))[fl];
            __half2* h0 = (__half2*)&p0;
            __half2* h1 = (__half2*)&p1;
            __half2* h2 = (__half2*)&p2;
            __half2* h3 = (__half2*)&p3;
            #pragma unroll
            for (int q = 0; q < 4; q++) {
                float2 f0 = __half22float2(h0[q]);
                float2 f1 = __half22float2(h1[q]);
                float2 f2 = __half22float2(h2[q]);
                float2 f3 = __half22float2(h3[q]);
                acc[2 * q]     += (f0.x + f1.x) + (f2.x + f3.x);
                acc[2 * q + 1] += (f0.y + f1.y) + (f2.y + f3.y);
            }
        }
        for (; i < cnt; i += 2) {
            int n = nodes[i];
            uint4 p = ((const uint4*)(g_Xh + (size_t)n * FT))[fl];
            __half2* hp = (__half2*)&p;
            #pragma unroll
            for (int q = 0; q < 4; q++) {
                float2 f = __half22float2(hp[q]);
                acc[2 * q]     += f.x;
                acc[2 * q + 1] += f.y;
            }
        }
        #pragma unroll
        for (int j = 0; j < 8; j++)
            acc[j] += __shfl_xor_sync(0xffffffffu, acc[j], 16);
        if (hw == 0) {
            uint4 o;
            __half2 h0 = __floats2half2_rn(acc[0], acc[1]);
            __half2 h1 = __floats2half2_rn(acc[2], acc[3]);
            __half2 h2 = __floats2half2_rn(acc[4], acc[5]);
            __half2 h3 = __floats2half2_rn(acc[6], acc[7]);
            o.x = *(unsigned*)&h0; o.y = *(unsigned*)&h1;
            o.z = *(unsigned*)&h2; o.w = *(unsigned*)&h3;
            ((uint4*)&s_h[w][0])[fl] = o;
        }
    } else {
        if (lane < 16) ((uint4*)&s_h[w][0])[lane] = make_uint4(0, 0, 0, 0);
    }
    __syncthreads();

    // ---- phase 2: [16,128] x [128,128] HMMA ----
    if (w < 8) {
        wmma::fragment<wmma::accumulator, 16, 16, 16, float> c;
        wmma::fill_fragment(c, 0.f);
        #pragma unroll
        for (int k = 0; k < FT; k += 16) {
            wmma::fragment<wmma::matrix_a, 16, 16, 16, __half, wmma::row_major> a;
            wmma::fragment<wmma::matrix_b, 16, 16, 16, __half, wmma::row_major> b;
            wmma::load_matrix_sync(a, &s_h[0][k], FT);
            wmma::load_matrix_sync(b, g_Wh + k * FT + w * 16, FT);
            wmma::mma_sync(c, a, b, c);
        }
        wmma::store_matrix_sync(&s_C[0][w * 16], c, FT, wmma::mem_row_major);
    }
    __syncthreads();

    // ---- phase 3: epilogue M = C / DE ----
    for (int idx = threadIdx.x; idx < EPB * FT; idx += 512) {
        int r = idx >> 7, j = idx & (FT - 1);
        int e2 = e0 + r;
        if (e2 < n_edges) {
            int de = g_de[e2];
            float m = (de > 0) ? s_C[r][j] / (float)de : 0.f;
            g_Mh[(size_t)e2 * FT + j] = __float2half(m);
        }
    }
}

// out[n] = relu( (sum_{e in node n} M[e]) / dv[n] + bias ).
// NOTE: no min-blocks bound — regs=32 / 16 blocks/SM measured 30.4us in R4;
// capping to 8 blocks (regs=60) measured 45.6us. Warp count wins here.
__global__ __launch_bounds__(FT) void scatter_out(const float* __restrict__ bias,
                                                  float* __restrict__ out) {
    int n = blockIdx.x;
    int t = threadIdx.x;
    int lane = t & 31;
    int g = t >> 5;
    int cnt = g_dv[n];
    const int* __restrict__ edges = g_csr + n * NODE_CAP;

    float4 acc = make_float4(0.f, 0.f, 0.f, 0.f);
    int i = g;
    for (; i + 16 <= cnt; i += 16) {   // 4 edges per group per iter
        int e0 = edges[i];
        int e1 = edges[i + 4];
        int e2 = edges[i + 8];
        int e3 = edges[i + 12];
        uint2 p0 = ((const uint2*)(g_Mh + (size_t)e0 * FT))[lane];
        uint2 p1 = ((const uint2*)(g_Mh + (size_t)e1 * FT))[lane];
        uint2 p2 = ((const uint2*)(g_Mh + (size_t)e2 * FT))[lane];
        uint2 p3 = ((const uint2*)(g_Mh + (size_t)e3 * FT))[lane];
        float2 a0 = __half22float2(*(__half2*)&p0.x), b0 = __half22float2(*(__half2*)&p0.y);
        float2 a1 = __half22float2(*(__half2*)&p1.x), b1 = __half22float2(*(__half2*)&p1.y);
        float2 a2 = __half22float2(*(__half2*)&p2.x), b2 = __half22float2(*(__half2*)&p2.y);
        float2 a3 = __half22float2(*(__half2*)&p3.x), b3 = __half22float2(*(__half2*)&p3.y);
        acc.x += (a0.x + a1.x) + (a2.x + a3.x);
        acc.y += (a0.y + a1.y) + (a2.y + a3.y);
        acc.z += (b0.x + b1.x) + (b2.x + b3.x);
        acc.w += (b0.y + b1.y) + (b2.y + b3.y);
    }
    for (; i < cnt; i += 4) {
        int e = edges[i];
        uint2 p = ((const uint2*)(g_Mh + (size_t)e * FT))[lane];
        float2 f0 = __half22float2(*(__half2*)&p.x);
        float2 f1 = __half22float2(*(__half2*)&p.y);
        acc.x += f0.x; acc.y += f0.y; acc.z += f1.x; acc.w += f1.y;
    }

    __shared__ float part[4][FT];
    ((float4*)part[g])[lane] = acc;
    __syncthreads();
    float v = (part[0][t] + part[1][t]) + (part[2][t] + part[3][t]);
    v = (cnt > 0) ? v / (float)cnt : 0.f;
    v += bias[t];
    out[(size_t)n * FT + t] = v > 0.f ? v : 0.f;
}

// ---------------------------------------------------------------------------
extern "C" void kernel_launch(void* const* d_in, const int* in_sizes, int n_in,
                              void* d_out, int out_size) {
    const float* X  = (const float*)d_in[0];   // [N, 128]
    const float* H  = (const float*)d_in[1];   // [N, E]
    const float* Wt = (const float*)d_in[2];   // [128, 128]
    const float* bs = (const float*)d_in[3];   // [128]
    float* out = (float*)d_out;                // [N, 128]

    int n_nodes = in_sizes[0] / FT;            // 20000
    int n_edges = in_sizes[1] / n_nodes;       // 5000
    if (n_nodes > MAX_N) n_nodes = MAX_N;
    if (n_edges > MAX_E) n_edges = MAX_E;

    int x4 = n_nodes * FT / 4;
    int w4 = FT * FT / 4;
    int ptot = x4 + w4;
    if (n_nodes > ptot) ptot = n_nodes;
    prep<<<(ptot + 255) / 256, 256>>>(X, Wt, x4, w4, n_nodes, n_edges);
    build_sparse<<<n_nodes, 256>>>(H, n_edges);
    gather_mma<<<(n_edges + EPB - 1) / EPB, 512>>>(n_edges);
    scatter_out<<<n_nodes, FT>>>(bs, out);
}

// round 8
// speedup vs baseline: 1.4794x; 1.0244x over previous
#include <cuda_runtime.h>
#include <cuda_fp16.h>
#include <mma.h>
using namespace nvcuda;

#define MAX_N 20000
#define MAX_E 5000
#define FT 128
#define NODE_CAP 128   // max edges per node (mean ~50, 11 sigma headroom)
#define EDGE_CAP 384   // max nodes per edge (mean ~200, 13 sigma headroom)
#define LIST_CAP 192   // per-row staging list (mean 50, 20 sigma headroom)
#define EPB 16         // edges per block in gather_mma

// ---- scratch (__device__ globals; no allocations allowed) ----
__device__ int    g_dv[MAX_N];               // node degree
__device__ int    g_de[MAX_E];               // edge degree
__device__ int    g_csr[MAX_N * NODE_CAP];   // edges per node
__device__ int    g_csc[MAX_E * EDGE_CAP];   // nodes per edge
__device__ __align__(16) __half g_Xh[MAX_N * FT];  // X in fp16
__device__ __align__(16) __half g_Wh[FT * FT];     // W in fp16
__device__ __align__(16) __half g_Mh[MAX_E * FT];  // M in fp16

// ---------------------------------------------------------------------------
// Fused: zero degree counters + convert X and W to fp16.
__global__ void prep(const float* __restrict__ X, const float* __restrict__ W,
                     int x4, int w4, int n_nodes, int n_edges) {
    int i = blockIdx.x * blockDim.x + threadIdx.x;
    if (i < n_nodes) g_dv[i] = 0;
    if (i < n_edges) g_de[i] = 0;
    if (i < x4) {
        float4 v = ((const float4*)X)[i];
        __half2 a = __floats2half2_rn(v.x, v.y);
        __half2 b = __floats2half2_rn(v.z, v.w);
        uint2 p; p.x = *(unsigned*)&a; p.y = *(unsigned*)&b;
        ((uint2*)g_Xh)[i] = p;
    } else if (i < x4 + w4) {
        int j = i - x4;
        float4 v = ((const float4*)W)[j];
        __half2 a = __floats2half2_rn(v.x, v.y);
        __half2 b = __floats2half2_rn(v.z, v.w);
        uint2 p; p.x = *(unsigned*)&a; p.y = *(unsigned*)&b;
        ((uint2*)g_Wh)[j] = p;
    }
}

// One block per node row of H; reads 400MB exactly once (streaming).
// Phase A: branch-free scan with WARP-UNIFORM trip count (all shuffles run
// with fully-active warps; loads predicated) -> compressed edge list in
// shared, no global atomics in the load loop. Phase B: parallel drain with
// independent ATOMG per entry.
__global__ __launch_bounds__(256, 8) void build_sparse(const float* __restrict__ H,
                                                       int n_edges) {
    int n = blockIdx.x;
    __shared__ int s_cnt;
    __shared__ int s_list[LIST_CAP];
    if (threadIdx.x == 0) s_cnt = 0;
    __syncthreads();

    const float4* row = (const float4*)(H + (size_t)n * n_edges);
    int nq = n_edges >> 2;
    int lane = threadIdx.x & 31;
    const float4 z4 = make_float4(0.f, 0.f, 0.f, 0.f);

    int stride = 4 * blockDim.x;
    int iters = (nq + stride - 1) / stride;   // uniform across the block

    for (int it = 0; it < iters; it++) {
        int i0 = threadIdx.x + it * stride;
        int i1 = i0 + blockDim.x;
        int i2 = i0 + 2 * blockDim.x;
        int i3 = i0 + 3 * blockDim.x;
        float4 v0 = (i0 < nq) ? __ldcs(&row[i0]) : z4;
        float4 v1 = (i1 < nq) ? __ldcs(&row[i1]) : z4;
        float4 v2 = (i2 < nq) ? __ldcs(&row[i2]) : z4;
        float4 v3 = (i3 < nq) ? __ldcs(&row[i3]) : z4;

        // per-thread nonzero count (branch-free)
        int c = (v0.x != 0.f) + (v0.y != 0.f) + (v0.z != 0.f) + (v0.w != 0.f)
              + (v1.x != 0.f) + (v1.y != 0.f) + (v1.z != 0.f) + (v1.w != 0.f)
              + (v2.x != 0.f) + (v2.y != 0.f) + (v2.z != 0.f) + (v2.w != 0.f)
              + (v3.x != 0.f) + (v3.y != 0.f) + (v3.z != 0.f) + (v3.w != 0.f);

        // warp inclusive scan of c (all 32 lanes always active)
        int pre = c;
        #pragma unroll
        for (int d = 1; d < 32; d <<= 1) {
            int t = __shfl_up_sync(0xffffffffu, pre, d);
            if (lane >= d) pre += t;
        }
        int total = __shfl_sync(0xffffffffu, pre, 31);
        if (total) {
            int base = 0;
            if (lane == 31) base = atomicAdd(&s_cnt, total);
            base = __shfl_sync(0xffffffffu, base, 31);
            int p = base + pre - c;   // exclusive offset for this lane
            #define EMIT(vv, ii) do { \
                int eb = (ii) << 2; \
                if ((vv).x != 0.f) { if (p < LIST_CAP) s_list[p] = eb;     p++; } \
                if ((vv).y != 0.f) { if (p < LIST_CAP) s_list[p] = eb + 1; p++; } \
                if ((vv).z != 0.f) { if (p < LIST_CAP) s_list[p] = eb + 2; p++; } \
                if ((vv).w != 0.f) { if (p < LIST_CAP) s_list[p] = eb + 3; p++; } \
            } while (0)
            EMIT(v0, i0); EMIT(v1, i1); EMIT(v2, i2); EMIT(v3, i3);
            #undef EMIT
        }
    }
    __syncthreads();

    int cnt = min(s_cnt, LIST_CAP);
    if (threadIdx.x == 0) g_dv[n] = min(cnt, NODE_CAP);
    for (int t = threadIdx.x; t < cnt; t += blockDim.x) {
        int e = s_list[t];
        if (t < NODE_CAP) g_csr[n * NODE_CAP + t] = e;
        int q = atomicAdd(&g_de[e], 1);
        if (q < EDGE_CAP) g_csc[e * EDGE_CAP + q] = n;
    }
}

// 16 edges per block. Phase 1: warp w gathers S[w] with 4 independent
// LDG.128 in flight per lane (launch_bounds(512,2) -> 64-reg budget).
// Phase 2: HMMA projection. Phase 3: /DE, store fp16.
__global__ __launch_bounds__(512, 2) void gather_mma(int n_edges) {
    __shared__ __half s_h[EPB][FT];
    __shared__ float  s_C[EPB][FT];

    int w = threadIdx.x >> 5;
    int lane = threadIdx.x & 31;
    int e0 = blockIdx.x * EPB;
    int e = e0 + w;

    // ---- phase 1: gather ----
    int hw = lane >> 4;        // half-warp -> node parity
    int fl = lane & 15;        // feature lane: 8 features
    if (e < n_edges) {
        int cnt = min(g_de[e], EDGE_CAP);
        const int* __restrict__ nodes = g_csc + e * EDGE_CAP;
        float acc[8];
        #pragma unroll
        for (int j = 0; j < 8; j++) acc[j] = 0.f;

        int i = hw;
        for (; i + 8 <= cnt; i += 8) {   // 4 nodes per half-warp per iter
            int n0 = nodes[i];
            int n1 = nodes[i + 2];
            int n2 = nodes[i + 4];
            int n3 = nodes[i + 6];
            uint4 p0 = ((const uint4*)(g_Xh + (size_t)n0 * FT))[fl];
            uint4 p1 = ((const uint4*)(g_Xh + (size_t)n1 * FT))[fl];
            uint4 p2 = ((const uint4*)(g_Xh + (size_t)n2 * FT))[fl];
            uint4 p3 = ((const uint4*)(g_Xh + (size_t)n3 * FT))[fl];
            __half2* h0 = (__half2*)&p0;
            __half2* h1 = (__half2*)&p1;
            __half2* h2 = (__half2*)&p2;
            __half2* h3 = (__half2*)&p3;
            #pragma unroll
            for (int q = 0; q < 4; q++) {
                float2 f0 = __half22float2(h0[q]);
                float2 f1 = __half22float2(h1[q]);
                float2 f2 = __half22float2(h2[q]);
                float2 f3 = __half22float2(h3[q]);
                acc[2 * q]     += (f0.x + f1.x) + (f2.x + f3.x);
                acc[2 * q + 1] += (f0.y + f1.y) + (f2.y + f3.y);
            }
        }
        for (; i < cnt; i += 2) {
            int n = nodes[i];
            uint4 p = ((const uint4*)(g_Xh + (size_t)n * FT))[fl];
            __half2* hp = (__half2*)&p;
            #pragma unroll
            for (int q = 0; q < 4; q++) {
                float2 f = __half22float2(hp[q]);
                acc[2 * q]     += f.x;
                acc[2 * q + 1] += f.y;
            }
        }
        #pragma unroll
        for (int j = 0; j < 8; j++)
            acc[j] += __shfl_xor_sync(0xffffffffu, acc[j], 16);
        if (hw == 0) {
            uint4 o;
            __half2 h0 = __floats2half2_rn(acc[0], acc[1]);
            __half2 h1 = __floats2half2_rn(acc[2], acc[3]);
            __half2 h2 = __floats2half2_rn(acc[4], acc[5]);
            __half2 h3 = __floats2half2_rn(acc[6], acc[7]);
            o.x = *(unsigned*)&h0; o.y = *(unsigned*)&h1;
            o.z = *(unsigned*)&h2; o.w = *(unsigned*)&h3;
            ((uint4*)&s_h[w][0])[fl] = o;
        }
    } else {
        if (lane < 16) ((uint4*)&s_h[w][0])[lane] = make_uint4(0, 0, 0, 0);
    }
    __syncthreads();

    // ---- phase 2: [16,128] x [128,128] HMMA ----
    if (w < 8) {
        wmma::fragment<wmma::accumulator, 16, 16, 16, float> c;
        wmma::fill_fragment(c, 0.f);
        #pragma unroll
        for (int k = 0; k < FT; k += 16) {
            wmma::fragment<wmma::matrix_a, 16, 16, 16, __half, wmma::row_major> a;
            wmma::fragment<wmma::matrix_b, 16, 16, 16, __half, wmma::row_major> b;
            wmma::load_matrix_sync(a, &s_h[0][k], FT);
            wmma::load_matrix_sync(b, g_Wh + k * FT + w * 16, FT);
            wmma::mma_sync(c, a, b, c);
        }
        wmma::store_matrix_sync(&s_C[0][w * 16], c, FT, wmma::mem_row_major);
    }
    __syncthreads();

    // ---- phase 3: epilogue M = C / DE ----
    for (int idx = threadIdx.x; idx < EPB * FT; idx += 512) {
        int r = idx >> 7, j = idx & (FT - 1);
        int e2 = e0 + r;
        if (e2 < n_edges) {
            int de = g_de[e2];
            float m = (de > 0) ? s_C[r][j] / (float)de : 0.f;
            g_Mh[(size_t)e2 * FT + j] = __float2half(m);
        }
    }
}

// out[n] = relu( (sum_{e in node n} M[e]) / dv[n] + bias ).
// NOTE: no min-blocks bound — regs=32 / 16 blocks/SM measured 30.4-30.9us;
// capping to 8 blocks (regs=60) measured 45.6us. Warp count wins here.
__global__ __launch_bounds__(FT) void scatter_out(const float* __restrict__ bias,
                                                  float* __restrict__ out) {
    int n = blockIdx.x;
    int t = threadIdx.x;
    int lane = t & 31;
    int g = t >> 5;
    int cnt = g_dv[n];
    const int* __restrict__ edges = g_csr + n * NODE_CAP;

    float4 acc = make_float4(0.f, 0.f, 0.f, 0.f);
    int i = g;
    for (; i + 16 <= cnt; i += 16) {   // 4 edges per group per iter
        int e0 = edges[i];
        int e1 = edges[i + 4];
        int e2 = edges[i + 8];
        int e3 = edges[i + 12];
        uint2 p0 = ((const uint2*)(g_Mh + (size_t)e0 * FT))[lane];
        uint2 p1 = ((const uint2*)(g_Mh + (size_t)e1 * FT))[lane];
        uint2 p2 = ((const uint2*)(g_Mh + (size_t)e2 * FT))[lane];
        uint2 p3 = ((const uint2*)(g_Mh + (size_t)e3 * FT))[lane];
        float2 a0 = __half22float2(*(__half2*)&p0.x), b0 = __half22float2(*(__half2*)&p0.y);
        float2 a1 = __half22float2(*(__half2*)&p1.x), b1 = __half22float2(*(__half2*)&p1.y);
        float2 a2 = __half22float2(*(__half2*)&p2.x), b2 = __half22float2(*(__half2*)&p2.y);
        float2 a3 = __half22float2(*(__half2*)&p3.x), b3 = __half22float2(*(__half2*)&p3.y);
        acc.x += (a0.x + a1.x) + (a2.x + a3.x);
        acc.y += (a0.y + a1.y) + (a2.y + a3.y);
        acc.z += (b0.x + b1.x) + (b2.x + b3.x);
        acc.w += (b0.y + b1.y) + (b2.y + b3.y);
    }
    for (; i < cnt; i += 4) {
        int e = edges[i];
        uint2 p = ((const uint2*)(g_Mh + (size_t)e * FT))[lane];
        float2 f0 = __half22float2(*(__half2*)&p.x);
        float2 f1 = __half22float2(*(__half2*)&p.y);
        acc.x += f0.x; acc.y += f0.y; acc.z += f1.x; acc.w += f1.y;
    }

    __shared__ float part[4][FT];
    ((float4*)part[g])[lane] = acc;
    __syncthreads();
    float v = (part[0][t] + part[1][t]) + (part[2][t] + part[3][t]);
    v = (cnt > 0) ? v / (float)cnt : 0.f;
    v += bias[t];
    out[(size_t)n * FT + t] = v > 0.f ? v : 0.f;
}

// ---------------------------------------------------------------------------
extern "C" void kernel_launch(void* const* d_in, const int* in_sizes, int n_in,
                              void* d_out, int out_size) {
    const float* X  = (const float*)d_in[0];   // [N, 128]
    const float* H  = (const float*)d_in[1];   // [N, E]
    const float* Wt = (const float*)d_in[2];   // [128, 128]
    const float* bs = (const float*)d_in[3];   // [128]
    float* out = (float*)d_out;                // [N, 128]

    int n_nodes = in_sizes[0] / FT;            // 20000
    int n_edges = in_sizes[1] / n_nodes;       // 5000
    if (n_nodes > MAX_N) n_nodes = MAX_N;
    if (n_edges > MAX_E) n_edges = MAX_E;

    int x4 = n_nodes * FT / 4;
    int w4 = FT * FT / 4;
    int ptot = x4 + w4;
    if (n_nodes > ptot) ptot = n_nodes;
    prep<<<(ptot + 255) / 256, 256>>>(X, Wt, x4, w4, n_nodes, n_edges);
    build_sparse<<<n_nodes, 256>>>(H, n_edges);
    gather_mma<<<(n_edges + EPB - 1) / EPB, 512>>>(n_edges);
    scatter_out<<<n_nodes, FT>>>(bs, out);
}